// round 10
// baseline (speedup 1.0000x reference)
#include <cuda_runtime.h>
#include <cstdint>

// VisibilityHeatmap: out[b,k] = in_bounds(coords[b,k]) && heatmaps[b,k,v,u] > 0.4
// coords: [B,K,2] int32 in (u,v) order; heatmaps: [B,K,H,W] f32.
// Output: [B,K] boolean mask as float32 (0.0f / 1.0f).
//
// Best-known config (16 blocks x 128, 4 outputs/thread, MLP=4) with a shortened
// address dependent-chain exploiting H=W=128:
//   in_bounds  = (unsigned)(u|v) < 128        (1 LOP + 1 ISETP vs 4 setp)
//   gather idx = ((v&127)<<7) | (u&127)       (always in-plane; OOB garbage is
//                                              masked after, matching the
//                                              reference's clip-then-mask)
#define H_DIM 128
#define W_DIM 128
#define PLANE (H_DIM * W_DIM)     // 16384
#define THRESH 0.4f

__global__ __launch_bounds__(128)
void visibility_kernel(const int4* __restrict__ coords4,
                       const float* __restrict__ heatmaps,
                       float4* __restrict__ out4)
{
    int t = blockIdx.x * 128 + threadIdx.x;    // 0..2047, outputs [4t, 4t+4)

    int4 c01 = coords4[2 * t];      // (u0,v0,u1,v1)
    int4 c23 = coords4[2 * t + 1];  // (u2,v2,u3,v3)

    int u0 = c01.x, v0 = c01.y, u1 = c01.z, v1 = c01.w;
    int u2 = c23.x, v2 = c23.y, u3 = c23.z, v3 = c23.w;

    // in-bounds iff both coords in [0,128): any negative -> sign bit set,
    // any >=128 -> bit>=7 set; OR preserves both conditions.
    bool ib0 = (unsigned)(u0 | v0) < 128u;
    bool ib1 = (unsigned)(u1 | v1) < 128u;
    bool ib2 = (unsigned)(u2 | v2) < 128u;
    bool ib3 = (unsigned)(u3 | v3) < 128u;

    const float* p = heatmaps + (size_t)(4 * t) * PLANE;

    // masked index: in-plane always; equals (v*W+u) exactly when in-bounds.
    int i0 = ((v0 & 127) << 7) | (u0 & 127);
    int i1 = ((v1 & 127) << 7) | (u1 & 127);
    int i2 = ((v2 & 127) << 7) | (u2 & 127);
    int i3 = ((v3 & 127) << 7) | (u3 & 127);

    // 4 independent gathers — front-batched, latency overlapped (MLP=4)
    float f0 = __ldg(p + 0 * PLANE + i0);
    float f1 = __ldg(p + 1 * PLANE + i1);
    float f2 = __ldg(p + 2 * PLANE + i2);
    float f3 = __ldg(p + 3 * PLANE + i3);

    float4 r;
    r.x = (ib0 && (f0 > THRESH)) ? 1.0f : 0.0f;
    r.y = (ib1 && (f1 > THRESH)) ? 1.0f : 0.0f;
    r.z = (ib2 && (f2 > THRESH)) ? 1.0f : 0.0f;
    r.w = (ib3 && (f3 > THRESH)) ? 1.0f : 0.0f;
    out4[t] = r;
}

extern "C" void kernel_launch(void* const* d_in, const int* in_sizes, int n_in,
                              void* d_out, int out_size)
{
    const int4*  coords4  = (const int4*)d_in[0];    // [B,K,2] int32, 2 pairs per int4
    const float* heatmaps = (const float*)d_in[1];   // [B,K,H,W] f32
    float4*      out4     = (float4*)d_out;          // [B,K] mask as f32

    // 8192 outputs / 4 per thread = 2048 threads = 16 blocks x 128
    visibility_kernel<<<16, 128>>>(coords4, heatmaps, out4);
}

// round 11
// speedup vs baseline: 1.0337x; 1.0337x over previous
#include <cuda_runtime.h>
#include <cstdint>

// VisibilityHeatmap: out[b,k] = in_bounds(coords[b,k]) && heatmaps[b,k,v,u] > 0.4
// coords: [B,K,2] int32 in (u,v) order; heatmaps: [B,K,H,W] f32.
// Output: [B,K] boolean mask as float32 (0.0f / 1.0f).
//
// FINAL. Floor established over R2-R9: all structural variants (1/2/4 outputs
// per thread, 8-128 blocks, addressing schemes) land in a 6.6-6.9us band whose
// spread is timer/run noise (byte-exact re-runs reproduce the band, not the
// draw). Workload is launch-overhead + dependent-gather-chain bound: DRAM 2%,
// issue 2%, no pipe contended. This variant has the shortest address chain:
//   in_bounds  = (unsigned)(u|v) < 128        (1 LOP + 1 ISETP)
//   gather idx = ((v&127)<<7) | (u&127)       (always in-plane; OOB masked
//                                              after, == reference clip+mask)
// Config: 16 blocks x 128 threads, 4 outputs/thread, MLP=4 gathers/thread.
#define H_DIM 128
#define W_DIM 128
#define PLANE (H_DIM * W_DIM)     // 16384
#define THRESH 0.4f

__global__ __launch_bounds__(128)
void visibility_kernel(const int4* __restrict__ coords4,
                       const float* __restrict__ heatmaps,
                       float4* __restrict__ out4)
{
    int t = blockIdx.x * 128 + threadIdx.x;    // 0..2047, outputs [4t, 4t+4)

    int4 c01 = coords4[2 * t];      // (u0,v0,u1,v1)
    int4 c23 = coords4[2 * t + 1];  // (u2,v2,u3,v3)

    int u0 = c01.x, v0 = c01.y, u1 = c01.z, v1 = c01.w;
    int u2 = c23.x, v2 = c23.y, u3 = c23.z, v3 = c23.w;

    // in-bounds iff both coords in [0,128): any negative -> sign bit set,
    // any >=128 -> bit>=7 set; OR preserves both conditions.
    bool ib0 = (unsigned)(u0 | v0) < 128u;
    bool ib1 = (unsigned)(u1 | v1) < 128u;
    bool ib2 = (unsigned)(u2 | v2) < 128u;
    bool ib3 = (unsigned)(u3 | v3) < 128u;

    const float* p = heatmaps + (size_t)(4 * t) * PLANE;

    // masked index: in-plane always; equals (v*W+u) exactly when in-bounds.
    int i0 = ((v0 & 127) << 7) | (u0 & 127);
    int i1 = ((v1 & 127) << 7) | (u1 & 127);
    int i2 = ((v2 & 127) << 7) | (u2 & 127);
    int i3 = ((v3 & 127) << 7) | (u3 & 127);

    // 4 independent gathers — front-batched, latency overlapped (MLP=4)
    float f0 = __ldg(p + 0 * PLANE + i0);
    float f1 = __ldg(p + 1 * PLANE + i1);
    float f2 = __ldg(p + 2 * PLANE + i2);
    float f3 = __ldg(p + 3 * PLANE + i3);

    float4 r;
    r.x = (ib0 && (f0 > THRESH)) ? 1.0f : 0.0f;
    r.y = (ib1 && (f1 > THRESH)) ? 1.0f : 0.0f;
    r.z = (ib2 && (f2 > THRESH)) ? 1.0f : 0.0f;
    r.w = (ib3 && (f3 > THRESH)) ? 1.0f : 0.0f;
    out4[t] = r;
}

extern "C" void kernel_launch(void* const* d_in, const int* in_sizes, int n_in,
                              void* d_out, int out_size)
{
    const int4*  coords4  = (const int4*)d_in[0];    // [B,K,2] int32, 2 pairs per int4
    const float* heatmaps = (const float*)d_in[1];   // [B,K,H,W] f32
    float4*      out4     = (float4*)d_out;          // [B,K] mask as f32

    // 8192 outputs / 4 per thread = 2048 threads = 16 blocks x 128
    visibility_kernel<<<16, 128>>>(coords4, heatmaps, out4);
}

// round 12
// speedup vs baseline: 1.0386x; 1.0048x over previous
#include <cuda_runtime.h>
#include <cstdint>

// VisibilityHeatmap: out[b,k] = in_bounds(coords[b,k]) && heatmaps[b,k,v,u] > 0.4
// coords: [B,K,2] int32 in (u,v) order; heatmaps: [B,K,H,W] f32.
// Output: [B,K] boolean mask as float32 (0.0f / 1.0f).
//
// FINAL (byte-identical to the R10 kernel, which drew 6.656us — tied best).
// Floor established over R2-R10: all structural variants (1/2/4 outputs per
// thread, 8-128 blocks, addressing schemes) draw from one 6.6-6.9us band;
// byte-exact re-runs span the whole band, so the spread is timer/run noise.
// Workload is launch-overhead + dependent-gather-chain bound: DRAM <=2.7%,
// issue <=2.9%, all pipes 0%. Shortest address chain of any variant:
//   in_bounds  = (unsigned)(u|v) < 128        (1 LOP + 1 ISETP)
//   gather idx = ((v&127)<<7) | (u&127)       (always in-plane; OOB masked
//                                              after, == reference clip+mask)
// Config: 16 blocks x 128 threads, 4 outputs/thread, MLP=4 gathers/thread.
#define H_DIM 128
#define W_DIM 128
#define PLANE (H_DIM * W_DIM)     // 16384
#define THRESH 0.4f

__global__ __launch_bounds__(128)
void visibility_kernel(const int4* __restrict__ coords4,
                       const float* __restrict__ heatmaps,
                       float4* __restrict__ out4)
{
    int t = blockIdx.x * 128 + threadIdx.x;    // 0..2047, outputs [4t, 4t+4)

    int4 c01 = coords4[2 * t];      // (u0,v0,u1,v1)
    int4 c23 = coords4[2 * t + 1];  // (u2,v2,u3,v3)

    int u0 = c01.x, v0 = c01.y, u1 = c01.z, v1 = c01.w;
    int u2 = c23.x, v2 = c23.y, u3 = c23.z, v3 = c23.w;

    // in-bounds iff both coords in [0,128): any negative -> sign bit set,
    // any >=128 -> bit>=7 set; OR preserves both conditions.
    bool ib0 = (unsigned)(u0 | v0) < 128u;
    bool ib1 = (unsigned)(u1 | v1) < 128u;
    bool ib2 = (unsigned)(u2 | v2) < 128u;
    bool ib3 = (unsigned)(u3 | v3) < 128u;

    const float* p = heatmaps + (size_t)(4 * t) * PLANE;

    // masked index: in-plane always; equals (v*W+u) exactly when in-bounds.
    int i0 = ((v0 & 127) << 7) | (u0 & 127);
    int i1 = ((v1 & 127) << 7) | (u1 & 127);
    int i2 = ((v2 & 127) << 7) | (u2 & 127);
    int i3 = ((v3 & 127) << 7) | (u3 & 127);

    // 4 independent gathers — front-batched, latency overlapped (MLP=4)
    float f0 = __ldg(p + 0 * PLANE + i0);
    float f1 = __ldg(p + 1 * PLANE + i1);
    float f2 = __ldg(p + 2 * PLANE + i2);
    float f3 = __ldg(p + 3 * PLANE + i3);

    float4 r;
    r.x = (ib0 && (f0 > THRESH)) ? 1.0f : 0.0f;
    r.y = (ib1 && (f1 > THRESH)) ? 1.0f : 0.0f;
    r.z = (ib2 && (f2 > THRESH)) ? 1.0f : 0.0f;
    r.w = (ib3 && (f3 > THRESH)) ? 1.0f : 0.0f;
    out4[t] = r;
}

extern "C" void kernel_launch(void* const* d_in, const int* in_sizes, int n_in,
                              void* d_out, int out_size)
{
    const int4*  coords4  = (const int4*)d_in[0];    // [B,K,2] int32, 2 pairs per int4
    const float* heatmaps = (const float*)d_in[1];   // [B,K,H,W] f32
    float4*      out4     = (float4*)d_out;          // [B,K] mask as f32

    // 8192 outputs / 4 per thread = 2048 threads = 16 blocks x 128
    visibility_kernel<<<16, 128>>>(coords4, heatmaps, out4);
}